// round 14
// baseline (speedup 1.0000x reference)
#include <cuda_runtime.h>
#include <cuda_bf16.h>

// Problem constants
#define BQ      8
#define NQ      8192
#define SQ      2048
#define NSAMP   64
#define CIN     64

// idx scratch: B*S*ns ints = 4MB (device global, no allocation)
__device__ int g_idx_buf[BQ * SQ * NSAMP];

// ---------------------------------------------------------------------------
// Kernel 1: ball query (warp per query, ordered early-exit scan) + new_xyz,
// inds, idx outputs.
// Distance formula replicates the reference exactly:
//   nn  = (x*x + y*y) + z*z            (separate rn mul/add, like XLA reduce)
//   dot = fma(z,cz, fma(y,cy, x*cx))   (cublas-style fma chain)
//   d2  = (qq + nn) - 2*dot
// ---------------------------------------------------------------------------
__global__ __launch_bounds__(128) void ballq_kernel(
    const float* __restrict__ xyz, const int* __restrict__ inds,
    float* __restrict__ o_newxyz, float* __restrict__ o_inds,
    float* __restrict__ o_idx)
{
    __shared__ int sl[4][NSAMP];
    const int w    = threadIdx.x >> 5;
    const int lane = threadIdx.x & 31;
    const int q    = blockIdx.x * 4 + w;
    const int b    = q >> 11;                 // q / SQ
    const float* bx = xyz + (size_t)b * NQ * 3;

    const int   ind = inds[q];
    const float cx = bx[ind * 3 + 0];
    const float cy = bx[ind * 3 + 1];
    const float cz = bx[ind * 3 + 2];
    const float qq = __fadd_rn(__fadd_rn(__fmul_rn(cx, cx), __fmul_rn(cy, cy)),
                               __fmul_rn(cz, cz));
    const float R2 = (float)(0.2 * 0.2);

    unsigned count = 0;
    for (int base = 0; base < NQ; base += 32) {
        const int i = base + lane;
        const float px = bx[i * 3 + 0];
        const float py = bx[i * 3 + 1];
        const float pz = bx[i * 3 + 2];
        const float nn = __fadd_rn(__fadd_rn(__fmul_rn(px, px), __fmul_rn(py, py)),
                                   __fmul_rn(pz, pz));
        const float dt = __fmaf_rn(pz, cz, __fmaf_rn(py, cy, __fmul_rn(px, cx)));
        const float d2 = __fsub_rn(__fadd_rn(qq, nn), __fmul_rn(2.0f, dt));
        const bool hit = d2 < R2;
        const unsigned m = __ballot_sync(0xffffffffu, hit);
        if (hit) {
            int pos = (int)count + __popc(m & ((1u << lane) - 1u));
            if (pos < NSAMP) sl[w][pos] = i;
        }
        count += (unsigned)__popc(m);
        if (count >= NSAMP) break;            // uniform across warp
    }
    __syncwarp();
    const int cnt = (count < NSAMP) ? (int)count : NSAMP;
    const int fpad = (cnt > 0) ? sl[w][0] : (NQ - 1);
    for (int j = cnt + lane; j < NSAMP; j += 32) sl[w][j] = fpad;
    __syncwarp();

    for (int j = lane; j < NSAMP; j += 32) {
        const int v = sl[w][j];
        g_idx_buf[(size_t)q * NSAMP + j] = v;
        o_idx[(size_t)q * NSAMP + j]     = (float)v;
    }
    if (lane == 0) {
        o_newxyz[q * 3 + 0] = cx;
        o_newxyz[q * 3 + 1] = cy;
        o_newxyz[q * 3 + 2] = cz;
        o_inds[q] = (float)ind;
    }
}

// ---------------------------------------------------------------------------
// Kernel 2: gather + MLP(68->64->64->128) + maxpool. One CTA (128 thr) per
// query. X tile in smem [64][68] (pitch 272B, 16B aligned -> conflict-free
// float4 broadcast loads). Each thread owns one output column: weight column
// in registers, 4 samples per step for 4-way FMA ILP.
// Column layout of X: [0..63]=features, [64..66]=(xyz-c)/R, [67]=0 pad.
// w0 rows therefore permuted: k<64 -> row k+3, k=64..66 -> rows 0..2.
// ---------------------------------------------------------------------------
__global__ __launch_bounds__(128) void mlp_kernel(
    const float* __restrict__ xyz, const float* __restrict__ feat,
    const int* __restrict__ inds,
    const float* __restrict__ w0, const float* __restrict__ s0, const float* __restrict__ t0,
    const float* __restrict__ w1, const float* __restrict__ s1, const float* __restrict__ t1,
    const float* __restrict__ w2, const float* __restrict__ s2, const float* __restrict__ t2,
    float* __restrict__ o_feat)
{
    __shared__ __align__(16) float sA[64][68];
    __shared__ __align__(16) float sB[64][68];
    __shared__ int   sidx[NSAMP];
    __shared__ float sc[3];

    const int q   = blockIdx.x;
    const int b   = q >> 11;
    const int tid = threadIdx.x;

    if (tid < NSAMP) sidx[tid] = g_idx_buf[(size_t)q * NSAMP + tid];
    if (tid == 64) {
        const int ind = inds[q];
        const float* p = xyz + ((size_t)b * NQ + ind) * 3;
        sc[0] = p[0]; sc[1] = p[1]; sc[2] = p[2];
    }
    __syncthreads();

    // ---- gather: 2 threads per sample, 8 float4 each ----
    {
        const int j  = tid >> 1;
        const int hh = tid & 1;
        const int p  = sidx[j];
        const float4* src = (const float4*)(feat + ((size_t)b * NQ + p) * CIN);
        float4* dst = (float4*)(&sA[j][0]);
        #pragma unroll
        for (int i = 0; i < 8; ++i) dst[hh * 8 + i] = src[hh * 8 + i];
        if (hh == 0) {
            const float* pz = xyz + ((size_t)b * NQ + p) * 3;
            sA[j][64] = (pz[0] - sc[0]) / 0.2f;
            sA[j][65] = (pz[1] - sc[1]) / 0.2f;
            sA[j][66] = (pz[2] - sc[2]) / 0.2f;
            sA[j][67] = 0.0f;
        }
    }
    __syncthreads();

    // ---- layer 1: K=68, N=64. thread = (col d, sample-half) ----
    {
        const int d    = tid & 63;
        const int half = tid >> 6;
        float wc[68];
        #pragma unroll
        for (int k = 0; k < 64; ++k) wc[k] = w0[(k + 3) * 64 + d];
        wc[64] = w0[0 * 64 + d];
        wc[65] = w0[1 * 64 + d];
        wc[66] = w0[2 * 64 + d];
        wc[67] = 0.0f;
        const float sd = s0[d], td = t0[d];
        const int sb = half * 32;
        for (int g = 0; g < 32; g += 4) {
            const float4* r0 = (const float4*)sA[sb + g + 0];
            const float4* r1 = (const float4*)sA[sb + g + 1];
            const float4* r2 = (const float4*)sA[sb + g + 2];
            const float4* r3 = (const float4*)sA[sb + g + 3];
            float a0 = 0.f, a1 = 0.f, a2 = 0.f, a3 = 0.f;
            #pragma unroll
            for (int k4 = 0; k4 < 17; ++k4) {
                float4 x;
                x = r0[k4];
                a0 = fmaf(x.x, wc[4*k4+0], a0); a0 = fmaf(x.y, wc[4*k4+1], a0);
                a0 = fmaf(x.z, wc[4*k4+2], a0); a0 = fmaf(x.w, wc[4*k4+3], a0);
                x = r1[k4];
                a1 = fmaf(x.x, wc[4*k4+0], a1); a1 = fmaf(x.y, wc[4*k4+1], a1);
                a1 = fmaf(x.z, wc[4*k4+2], a1); a1 = fmaf(x.w, wc[4*k4+3], a1);
                x = r2[k4];
                a2 = fmaf(x.x, wc[4*k4+0], a2); a2 = fmaf(x.y, wc[4*k4+1], a2);
                a2 = fmaf(x.z, wc[4*k4+2], a2); a2 = fmaf(x.w, wc[4*k4+3], a2);
                x = r3[k4];
                a3 = fmaf(x.x, wc[4*k4+0], a3); a3 = fmaf(x.y, wc[4*k4+1], a3);
                a3 = fmaf(x.z, wc[4*k4+2], a3); a3 = fmaf(x.w, wc[4*k4+3], a3);
            }
            sB[sb + g + 0][d] = fmaxf(fmaf(a0, sd, td), 0.0f);
            sB[sb + g + 1][d] = fmaxf(fmaf(a1, sd, td), 0.0f);
            sB[sb + g + 2][d] = fmaxf(fmaf(a2, sd, td), 0.0f);
            sB[sb + g + 3][d] = fmaxf(fmaf(a3, sd, td), 0.0f);
        }
    }
    __syncthreads();

    // ---- layer 2: K=64, N=64. sB -> sA ----
    {
        const int d    = tid & 63;
        const int half = tid >> 6;
        float wc[64];
        #pragma unroll
        for (int k = 0; k < 64; ++k) wc[k] = w1[k * 64 + d];
        const float sd = s1[d], td = t1[d];
        const int sb = half * 32;
        for (int g = 0; g < 32; g += 4) {
            const float4* r0 = (const float4*)sB[sb + g + 0];
            const float4* r1 = (const float4*)sB[sb + g + 1];
            const float4* r2 = (const float4*)sB[sb + g + 2];
            const float4* r3 = (const float4*)sB[sb + g + 3];
            float a0 = 0.f, a1 = 0.f, a2 = 0.f, a3 = 0.f;
            #pragma unroll
            for (int k4 = 0; k4 < 16; ++k4) {
                float4 x;
                x = r0[k4];
                a0 = fmaf(x.x, wc[4*k4+0], a0); a0 = fmaf(x.y, wc[4*k4+1], a0);
                a0 = fmaf(x.z, wc[4*k4+2], a0); a0 = fmaf(x.w, wc[4*k4+3], a0);
                x = r1[k4];
                a1 = fmaf(x.x, wc[4*k4+0], a1); a1 = fmaf(x.y, wc[4*k4+1], a1);
                a1 = fmaf(x.z, wc[4*k4+2], a1); a1 = fmaf(x.w, wc[4*k4+3], a1);
                x = r2[k4];
                a2 = fmaf(x.x, wc[4*k4+0], a2); a2 = fmaf(x.y, wc[4*k4+1], a2);
                a2 = fmaf(x.z, wc[4*k4+2], a2); a2 = fmaf(x.w, wc[4*k4+3], a2);
                x = r3[k4];
                a3 = fmaf(x.x, wc[4*k4+0], a3); a3 = fmaf(x.y, wc[4*k4+1], a3);
                a3 = fmaf(x.z, wc[4*k4+2], a3); a3 = fmaf(x.w, wc[4*k4+3], a3);
            }
            sA[sb + g + 0][d] = fmaxf(fmaf(a0, sd, td), 0.0f);
            sA[sb + g + 1][d] = fmaxf(fmaf(a1, sd, td), 0.0f);
            sA[sb + g + 2][d] = fmaxf(fmaf(a2, sd, td), 0.0f);
            sA[sb + g + 3][d] = fmaxf(fmaf(a3, sd, td), 0.0f);
        }
    }
    __syncthreads();

    // ---- layer 3 + maxpool: K=64, N=128. thread = column d, all 64 samples.
    // relu >= 0 so max-init at 0 equals max over relu outputs. ----
    {
        const int d = tid;
        float wc[64];
        #pragma unroll
        for (int k = 0; k < 64; ++k) wc[k] = w2[k * 128 + d];
        const float sd = s2[d], td = t2[d];
        float mx = 0.0f;
        for (int g = 0; g < 64; g += 4) {
            const float4* r0 = (const float4*)sA[g + 0];
            const float4* r1 = (const float4*)sA[g + 1];
            const float4* r2 = (const float4*)sA[g + 2];
            const float4* r3 = (const float4*)sA[g + 3];
            float a0 = 0.f, a1 = 0.f, a2 = 0.f, a3 = 0.f;
            #pragma unroll
            for (int k4 = 0; k4 < 16; ++k4) {
                float4 x;
                x = r0[k4];
                a0 = fmaf(x.x, wc[4*k4+0], a0); a0 = fmaf(x.y, wc[4*k4+1], a0);
                a0 = fmaf(x.z, wc[4*k4+2], a0); a0 = fmaf(x.w, wc[4*k4+3], a0);
                x = r1[k4];
                a1 = fmaf(x.x, wc[4*k4+0], a1); a1 = fmaf(x.y, wc[4*k4+1], a1);
                a1 = fmaf(x.z, wc[4*k4+2], a1); a1 = fmaf(x.w, wc[4*k4+3], a1);
                x = r2[k4];
                a2 = fmaf(x.x, wc[4*k4+0], a2); a2 = fmaf(x.y, wc[4*k4+1], a2);
                a2 = fmaf(x.z, wc[4*k4+2], a2); a2 = fmaf(x.w, wc[4*k4+3], a2);
                x = r3[k4];
                a3 = fmaf(x.x, wc[4*k4+0], a3); a3 = fmaf(x.y, wc[4*k4+1], a3);
                a3 = fmaf(x.z, wc[4*k4+2], a3); a3 = fmaf(x.w, wc[4*k4+3], a3);
            }
            mx = fmaxf(mx, fmaf(a0, sd, td));
            mx = fmaxf(mx, fmaf(a1, sd, td));
            mx = fmaxf(mx, fmaf(a2, sd, td));
            mx = fmaxf(mx, fmaf(a3, sd, td));
        }
        o_feat[(size_t)q * 128 + d] = mx;
    }
}

// ---------------------------------------------------------------------------
// Launch. Output layout (float32, tuple flattened in return order):
//   [ new_xyz (B*S*3) | new_features (B*S*128) | inds (B*S) | idx (B*S*64) ]
// ---------------------------------------------------------------------------
extern "C" void kernel_launch(void* const* d_in, const int* in_sizes, int n_in,
                              void* d_out, int out_size)
{
    const float* xyz  = (const float*)d_in[0];
    const float* feat = (const float*)d_in[1];
    const int*   inds = (const int*)  d_in[2];
    const float* w0 = (const float*)d_in[3];
    const float* s0 = (const float*)d_in[4];
    const float* t0 = (const float*)d_in[5];
    const float* w1 = (const float*)d_in[6];
    const float* s1 = (const float*)d_in[7];
    const float* t1 = (const float*)d_in[8];
    const float* w2 = (const float*)d_in[9];
    const float* s2 = (const float*)d_in[10];
    const float* t2 = (const float*)d_in[11];

    float* out       = (float*)d_out;
    float* o_newxyz  = out;
    float* o_feat    = out + (size_t)BQ * SQ * 3;
    float* o_inds    = o_feat + (size_t)BQ * SQ * 128;
    float* o_idx     = o_inds + (size_t)BQ * SQ;

    ballq_kernel<<<(BQ * SQ) / 4, 128>>>(xyz, inds, o_newxyz, o_inds, o_idx);
    mlp_kernel<<<BQ * SQ, 128>>>(xyz, feat, inds,
                                 w0, s0, t0, w1, s1, t1, w2, s2, t2,
                                 o_feat);
}

// round 15
// speedup vs baseline: 1.0059x; 1.0059x over previous
#include <cuda_runtime.h>
#include <cuda_bf16.h>

// Problem constants
#define BQ      8
#define NQ      8192
#define SQ      2048
#define NSAMP   64
#define CIN     64

// idx scratch: B*S*ns ints = 4MB (device global, no allocation)
__device__ int g_idx_buf[BQ * SQ * NSAMP];

// ---------------------------------------------------------------------------
// Kernel 1: ball query (warp per query, ordered early-exit scan) + new_xyz,
// inds, idx outputs.
// Distance formula replicates the reference exactly:
//   nn  = (x*x + y*y) + z*z            (separate rn mul/add, like XLA reduce)
//   dot = fma(z,cz, fma(y,cy, x*cx))   (cublas-style fma chain)
//   d2  = (qq + nn) - 2*dot
// ---------------------------------------------------------------------------
__global__ __launch_bounds__(128) void ballq_kernel(
    const float* __restrict__ xyz, const int* __restrict__ inds,
    float* __restrict__ o_newxyz, float* __restrict__ o_inds,
    float* __restrict__ o_idx)
{
    __shared__ int sl[4][NSAMP];
    const int w    = threadIdx.x >> 5;
    const int lane = threadIdx.x & 31;
    const int q    = blockIdx.x * 4 + w;
    const int b    = q >> 11;                 // q / SQ
    const float* bx = xyz + (size_t)b * NQ * 3;

    const int   ind = inds[q];
    const float cx = bx[ind * 3 + 0];
    const float cy = bx[ind * 3 + 1];
    const float cz = bx[ind * 3 + 2];
    const float qq = __fadd_rn(__fadd_rn(__fmul_rn(cx, cx), __fmul_rn(cy, cy)),
                               __fmul_rn(cz, cz));
    const float R2 = (float)(0.2 * 0.2);

    unsigned count = 0;
    for (int base = 0; base < NQ; base += 32) {
        const int i = base + lane;
        const float px = bx[i * 3 + 0];
        const float py = bx[i * 3 + 1];
        const float pz = bx[i * 3 + 2];
        const float nn = __fadd_rn(__fadd_rn(__fmul_rn(px, px), __fmul_rn(py, py)),
                                   __fmul_rn(pz, pz));
        const float dt = __fmaf_rn(pz, cz, __fmaf_rn(py, cy, __fmul_rn(px, cx)));
        const float d2 = __fsub_rn(__fadd_rn(qq, nn), __fmul_rn(2.0f, dt));
        const bool hit = d2 < R2;
        const unsigned m = __ballot_sync(0xffffffffu, hit);
        if (hit) {
            int pos = (int)count + __popc(m & ((1u << lane) - 1u));
            if (pos < NSAMP) sl[w][pos] = i;
        }
        count += (unsigned)__popc(m);
        if (count >= NSAMP) break;            // uniform across warp
    }
    __syncwarp();
    const int cnt = (count < NSAMP) ? (int)count : NSAMP;
    const int fpad = (cnt > 0) ? sl[w][0] : (NQ - 1);
    for (int j = cnt + lane; j < NSAMP; j += 32) sl[w][j] = fpad;
    __syncwarp();

    for (int j = lane; j < NSAMP; j += 32) {
        const int v = sl[w][j];
        g_idx_buf[(size_t)q * NSAMP + j] = v;
        o_idx[(size_t)q * NSAMP + j]     = (float)v;
    }
    if (lane == 0) {
        o_newxyz[q * 3 + 0] = cx;
        o_newxyz[q * 3 + 1] = cy;
        o_newxyz[q * 3 + 2] = cz;
        o_inds[q] = (float)ind;
    }
}

// ---------------------------------------------------------------------------
// Kernel 2: gather + MLP(68->64->64->128) + maxpool. One CTA (128 thr) per
// query. X tile in smem [64][68] (pitch 272B, 16B aligned -> conflict-free
// float4 broadcast loads). Each thread owns one output column: weight column
// in registers, 4 samples per step for 4-way FMA ILP.
// Column layout of X: [0..63]=features, [64..66]=(xyz-c)/R, [67]=0 pad.
// w0 rows therefore permuted: k<64 -> row k+3, k=64..66 -> rows 0..2.
// ---------------------------------------------------------------------------
__global__ __launch_bounds__(128) void mlp_kernel(
    const float* __restrict__ xyz, const float* __restrict__ feat,
    const int* __restrict__ inds,
    const float* __restrict__ w0, const float* __restrict__ s0, const float* __restrict__ t0,
    const float* __restrict__ w1, const float* __restrict__ s1, const float* __restrict__ t1,
    const float* __restrict__ w2, const float* __restrict__ s2, const float* __restrict__ t2,
    float* __restrict__ o_feat)
{
    __shared__ __align__(16) float sA[64][68];
    __shared__ __align__(16) float sB[64][68];
    __shared__ int   sidx[NSAMP];
    __shared__ float sc[3];

    const int q   = blockIdx.x;
    const int b   = q >> 11;
    const int tid = threadIdx.x;

    if (tid < NSAMP) sidx[tid] = g_idx_buf[(size_t)q * NSAMP + tid];
    if (tid == 64) {
        const int ind = inds[q];
        const float* p = xyz + ((size_t)b * NQ + ind) * 3;
        sc[0] = p[0]; sc[1] = p[1]; sc[2] = p[2];
    }
    __syncthreads();

    // ---- gather: 2 threads per sample, 8 float4 each ----
    {
        const int j  = tid >> 1;
        const int hh = tid & 1;
        const int p  = sidx[j];
        const float4* src = (const float4*)(feat + ((size_t)b * NQ + p) * CIN);
        float4* dst = (float4*)(&sA[j][0]);
        #pragma unroll
        for (int i = 0; i < 8; ++i) dst[hh * 8 + i] = src[hh * 8 + i];
        if (hh == 0) {
            const float* pz = xyz + ((size_t)b * NQ + p) * 3;
            sA[j][64] = (pz[0] - sc[0]) / 0.2f;
            sA[j][65] = (pz[1] - sc[1]) / 0.2f;
            sA[j][66] = (pz[2] - sc[2]) / 0.2f;
            sA[j][67] = 0.0f;
        }
    }
    __syncthreads();

    // ---- layer 1: K=68, N=64. thread = (col d, sample-half) ----
    {
        const int d    = tid & 63;
        const int half = tid >> 6;
        float wc[68];
        #pragma unroll
        for (int k = 0; k < 64; ++k) wc[k] = w0[(k + 3) * 64 + d];
        wc[64] = w0[0 * 64 + d];
        wc[65] = w0[1 * 64 + d];
        wc[66] = w0[2 * 64 + d];
        wc[67] = 0.0f;
        const float sd = s0[d], td = t0[d];
        const int sb = half * 32;
        for (int g = 0; g < 32; g += 4) {
            const float4* r0 = (const float4*)sA[sb + g + 0];
            const float4* r1 = (const float4*)sA[sb + g + 1];
            const float4* r2 = (const float4*)sA[sb + g + 2];
            const float4* r3 = (const float4*)sA[sb + g + 3];
            float a0 = 0.f, a1 = 0.f, a2 = 0.f, a3 = 0.f;
            #pragma unroll
            for (int k4 = 0; k4 < 17; ++k4) {
                float4 x;
                x = r0[k4];
                a0 = fmaf(x.x, wc[4*k4+0], a0); a0 = fmaf(x.y, wc[4*k4+1], a0);
                a0 = fmaf(x.z, wc[4*k4+2], a0); a0 = fmaf(x.w, wc[4*k4+3], a0);
                x = r1[k4];
                a1 = fmaf(x.x, wc[4*k4+0], a1); a1 = fmaf(x.y, wc[4*k4+1], a1);
                a1 = fmaf(x.z, wc[4*k4+2], a1); a1 = fmaf(x.w, wc[4*k4+3], a1);
                x = r2[k4];
                a2 = fmaf(x.x, wc[4*k4+0], a2); a2 = fmaf(x.y, wc[4*k4+1], a2);
                a2 = fmaf(x.z, wc[4*k4+2], a2); a2 = fmaf(x.w, wc[4*k4+3], a2);
                x = r3[k4];
                a3 = fmaf(x.x, wc[4*k4+0], a3); a3 = fmaf(x.y, wc[4*k4+1], a3);
                a3 = fmaf(x.z, wc[4*k4+2], a3); a3 = fmaf(x.w, wc[4*k4+3], a3);
            }
            sB[sb + g + 0][d] = fmaxf(fmaf(a0, sd, td), 0.0f);
            sB[sb + g + 1][d] = fmaxf(fmaf(a1, sd, td), 0.0f);
            sB[sb + g + 2][d] = fmaxf(fmaf(a2, sd, td), 0.0f);
            sB[sb + g + 3][d] = fmaxf(fmaf(a3, sd, td), 0.0f);
        }
    }
    __syncthreads();

    // ---- layer 2: K=64, N=64. sB -> sA ----
    {
        const int d    = tid & 63;
        const int half = tid >> 6;
        float wc[64];
        #pragma unroll
        for (int k = 0; k < 64; ++k) wc[k] = w1[k * 64 + d];
        const float sd = s1[d], td = t1[d];
        const int sb = half * 32;
        for (int g = 0; g < 32; g += 4) {
            const float4* r0 = (const float4*)sB[sb + g + 0];
            const float4* r1 = (const float4*)sB[sb + g + 1];
            const float4* r2 = (const float4*)sB[sb + g + 2];
            const float4* r3 = (const float4*)sB[sb + g + 3];
            float a0 = 0.f, a1 = 0.f, a2 = 0.f, a3 = 0.f;
            #pragma unroll
            for (int k4 = 0; k4 < 16; ++k4) {
                float4 x;
                x = r0[k4];
                a0 = fmaf(x.x, wc[4*k4+0], a0); a0 = fmaf(x.y, wc[4*k4+1], a0);
                a0 = fmaf(x.z, wc[4*k4+2], a0); a0 = fmaf(x.w, wc[4*k4+3], a0);
                x = r1[k4];
                a1 = fmaf(x.x, wc[4*k4+0], a1); a1 = fmaf(x.y, wc[4*k4+1], a1);
                a1 = fmaf(x.z, wc[4*k4+2], a1); a1 = fmaf(x.w, wc[4*k4+3], a1);
                x = r2[k4];
                a2 = fmaf(x.x, wc[4*k4+0], a2); a2 = fmaf(x.y, wc[4*k4+1], a2);
                a2 = fmaf(x.z, wc[4*k4+2], a2); a2 = fmaf(x.w, wc[4*k4+3], a2);
                x = r3[k4];
                a3 = fmaf(x.x, wc[4*k4+0], a3); a3 = fmaf(x.y, wc[4*k4+1], a3);
                a3 = fmaf(x.z, wc[4*k4+2], a3); a3 = fmaf(x.w, wc[4*k4+3], a3);
            }
            sA[sb + g + 0][d] = fmaxf(fmaf(a0, sd, td), 0.0f);
            sA[sb + g + 1][d] = fmaxf(fmaf(a1, sd, td), 0.0f);
            sA[sb + g + 2][d] = fmaxf(fmaf(a2, sd, td), 0.0f);
            sA[sb + g + 3][d] = fmaxf(fmaf(a3, sd, td), 0.0f);
        }
    }
    __syncthreads();

    // ---- layer 3 + maxpool: K=64, N=128. thread = column d, all 64 samples.
    // relu >= 0 so max-init at 0 equals max over relu outputs. ----
    {
        const int d = tid;
        float wc[64];
        #pragma unroll
        for (int k = 0; k < 64; ++k) wc[k] = w2[k * 128 + d];
        const float sd = s2[d], td = t2[d];
        float mx = 0.0f;
        for (int g = 0; g < 64; g += 4) {
            const float4* r0 = (const float4*)sA[g + 0];
            const float4* r1 = (const float4*)sA[g + 1];
            const float4* r2 = (const float4*)sA[g + 2];
            const float4* r3 = (const float4*)sA[g + 3];
            float a0 = 0.f, a1 = 0.f, a2 = 0.f, a3 = 0.f;
            #pragma unroll
            for (int k4 = 0; k4 < 16; ++k4) {
                float4 x;
                x = r0[k4];
                a0 = fmaf(x.x, wc[4*k4+0], a0); a0 = fmaf(x.y, wc[4*k4+1], a0);
                a0 = fmaf(x.z, wc[4*k4+2], a0); a0 = fmaf(x.w, wc[4*k4+3], a0);
                x = r1[k4];
                a1 = fmaf(x.x, wc[4*k4+0], a1); a1 = fmaf(x.y, wc[4*k4+1], a1);
                a1 = fmaf(x.z, wc[4*k4+2], a1); a1 = fmaf(x.w, wc[4*k4+3], a1);
                x = r2[k4];
                a2 = fmaf(x.x, wc[4*k4+0], a2); a2 = fmaf(x.y, wc[4*k4+1], a2);
                a2 = fmaf(x.z, wc[4*k4+2], a2); a2 = fmaf(x.w, wc[4*k4+3], a2);
                x = r3[k4];
                a3 = fmaf(x.x, wc[4*k4+0], a3); a3 = fmaf(x.y, wc[4*k4+1], a3);
                a3 = fmaf(x.z, wc[4*k4+2], a3); a3 = fmaf(x.w, wc[4*k4+3], a3);
            }
            mx = fmaxf(mx, fmaf(a0, sd, td));
            mx = fmaxf(mx, fmaf(a1, sd, td));
            mx = fmaxf(mx, fmaf(a2, sd, td));
            mx = fmaxf(mx, fmaf(a3, sd, td));
        }
        o_feat[(size_t)q * 128 + d] = mx;
    }
}

// ---------------------------------------------------------------------------
// Launch. Output layout (float32, tuple flattened in return order):
//   [ new_xyz (B*S*3) | new_features (B*S*128) | inds (B*S) | idx (B*S*64) ]
// ---------------------------------------------------------------------------
extern "C" void kernel_launch(void* const* d_in, const int* in_sizes, int n_in,
                              void* d_out, int out_size)
{
    const float* xyz  = (const float*)d_in[0];
    const float* feat = (const float*)d_in[1];
    const int*   inds = (const int*)  d_in[2];
    const float* w0 = (const float*)d_in[3];
    const float* s0 = (const float*)d_in[4];
    const float* t0 = (const float*)d_in[5];
    const float* w1 = (const float*)d_in[6];
    const float* s1 = (const float*)d_in[7];
    const float* t1 = (const float*)d_in[8];
    const float* w2 = (const float*)d_in[9];
    const float* s2 = (const float*)d_in[10];
    const float* t2 = (const float*)d_in[11];

    float* out       = (float*)d_out;
    float* o_newxyz  = out;
    float* o_feat    = out + (size_t)BQ * SQ * 3;
    float* o_inds    = o_feat + (size_t)BQ * SQ * 128;
    float* o_idx     = o_inds + (size_t)BQ * SQ;

    ballq_kernel<<<(BQ * SQ) / 4, 128>>>(xyz, inds, o_newxyz, o_inds, o_idx);
    mlp_kernel<<<BQ * SQ, 128>>>(xyz, feat, inds,
                                 w0, s0, t0, w1, s1, t1, w2, s2, t2,
                                 o_feat);
}